// round 10
// baseline (speedup 1.0000x reference)
#include <cuda_runtime.h>

#define NFSZ 1001
#define HSZ   256
#define BSZ   64
#define FD    128
#define INCH  16
#define G4    1024   // 4*H
#define INS0  144    // FD + INCH

// device-global scratch (allocation-free rule)
__device__ float g_Gf[NFSZ * G4];                // pre-scaled f-side gate pre-acts
__device__ unsigned long long g_mb[BSZ * 1024];  // layer0->layer1 mailbox {tag,val}

__device__ __forceinline__ float ex2f(float x) {
    float y; asm("ex2.approx.f32 %0, %1;" : "=f"(y) : "f"(x)); return y;
}
__device__ __forceinline__ float rcpf(float x) {
    float y; asm("rcp.approx.f32 %0, %1;" : "=f"(y) : "f"(x)); return y;
}
__device__ __forceinline__ float negabsf(float x) {
    return __int_as_float(__float_as_int(x) | 0x80000000);
}
__device__ __forceinline__ unsigned long long ldv64(const unsigned long long* p) {
    unsigned long long v;
    asm volatile("ld.volatile.global.b64 %0, [%1];" : "=l"(v) : "l"(p));
    return v;
}
__device__ __forceinline__ void stv64(unsigned long long* p, unsigned long long v) {
    asm volatile("st.volatile.global.b64 [%0], %1;" :: "l"(p), "l"(v) : "memory");
}
__device__ __forceinline__ unsigned smaddr(const void* p) {
    unsigned a;
    asm("{.reg .u64 t; cvta.to.shared.u64 t, %1; cvt.u32.u64 %0, t;}"
        : "=r"(a) : "l"(p));
    return a;
}
__device__ __forceinline__ unsigned long long ldvs64(unsigned a) {
    unsigned long long v;
    asm volatile("ld.volatile.shared.b64 %0, [%1];" : "=l"(v) : "r"(a));
    return v;
}
__device__ __forceinline__ void stvs64(unsigned a, unsigned long long v) {
    asm volatile("st.volatile.shared.b64 [%0], %1;" :: "r"(a), "l"(v));
}
__device__ __forceinline__ unsigned long long packtv(unsigned tag, float val) {
    return ((unsigned long long)tag << 32) | (unsigned)__float_as_int(val);
}
__device__ __forceinline__ float valof(unsigned long long v) {
    return __int_as_float((int)(unsigned)v);
}

#define L2E   1.4426950408889634f
#define NL2E2 -2.8853900817779268f

// ---------------- precompute: Gf = scale * (f @ Wf^T) ----------------
__global__ __launch_bounds__(256) void gf_kernel(const float* __restrict__ f,
                                                 const float* __restrict__ Wih0) {
    __shared__ float Wc[256][33];
    __shared__ float fs[8][32];
    const int tid = threadIdx.x;
    const int t0  = blockIdx.x * 8;
    const int gb  = blockIdx.y * 256;

    float acc[8] = {0.f,0.f,0.f,0.f,0.f,0.f,0.f,0.f};
    for (int kc = 0; kc < FD; kc += 32) {
        #pragma unroll
        for (int i = 0; i < 32; i++) {
            int e  = i * 256 + tid;
            int gl = e >> 5, kk = e & 31;
            Wc[gl][kk] = Wih0[(gb + gl) * INS0 + kc + kk];
        }
        {
            int tt = tid >> 5, kk = tid & 31;
            int t = t0 + tt;
            fs[tt][kk] = (t < NFSZ) ? f[t * FD + kc + kk] : 0.f;
        }
        __syncthreads();
        #pragma unroll 8
        for (int kk = 0; kk < 32; kk++) {
            float w = Wc[tid][kk];
            #pragma unroll
            for (int tt = 0; tt < 8; tt++) acc[tt] = fmaf(fs[tt][kk], w, acc[tt]);
        }
        __syncthreads();
    }
    float scale = (blockIdx.y == 2) ? NL2E2 : -L2E;
    #pragma unroll
    for (int tt = 0; tt < 8; tt++) {
        int t = t0 + tt;
        if (t < NFSZ) g_Gf[t * G4 + gb + tid] = acc[tt] * scale;
    }
}

// ---------------- main LSTM: 2 CTAs per batch ----------------
// blk even -> role A (layer0: 256 thr, 1 unit/thread, __syncthreads lockstep,
//                     proven R5 structure).
// blk odd  -> role B (layer1 = warps 0-3 with bar.sync 1, layer2 = warps 4-7
//                     with bar.sync 2 — independent phases).
// Links: layer0->1 tagged gmem ring; layer1->2 tagged smem ring.

__global__ __launch_bounds__(256, 1) void lstm_kernel(
    const float* __restrict__ x,
    const float* __restrict__ Wih0, const float* __restrict__ Whh0,
    const float* __restrict__ bih0, const float* __restrict__ bhh0,
    const float* __restrict__ Whr0,
    const float* __restrict__ Wih1, const float* __restrict__ Whh1,
    const float* __restrict__ bih1, const float* __restrict__ bhh1,
    const float* __restrict__ Whr1,
    const float* __restrict__ Wih2, const float* __restrict__ Whh2,
    const float* __restrict__ bih2, const float* __restrict__ bhh2,
    const float* __restrict__ Whr2,
    float* __restrict__ out)
{
    __shared__ __align__(16) float partA[2][8];      // role A warp partials
    __shared__ __align__(16) float partB[2][2][16];  // [parity][layer][16]
    __shared__ unsigned long long fwd[NFSZ];         // layer1->2 tagged ring

    const int b    = blockIdx.x >> 1;
    const int role = blockIdx.x & 1;
    const int tid  = threadIdx.x;

    if (role == 0) {
        // ================= ROLE A : layer 0 (R5-proven) =================
        const int u    = tid;
        const int warp = tid >> 5;
        const int lane = tid & 31;

        float whh_s[4], base_s[4];
        #pragma unroll
        for (int g = 0; g < 4; g++) {
            int idx  = g * HSZ + u;
            float sc = (g == 2) ? NL2E2 : -L2E;
            whh_s[g] = Whh0[idx] * sc;
            float acc = bih0[idx] + bhh0[idx];
            #pragma unroll
            for (int kk = 0; kk < INCH; kk++)
                acc = fmaf(x[b * INCH + kk], Wih0[idx * INS0 + FD + kk], acc);
            base_s[g] = acc * sc;
        }
        const float whr = Whr0[u];
        float c = 0.f;

        if (tid < 8) { partA[0][tid] = 0.f; partA[1][tid] = 0.f; }
        __syncthreads();

        float gfc[4], gfn[4];
        #pragma unroll
        for (int g = 0; g < 4; g++) gfc[g] = g_Gf[g * HSZ + u] + base_s[g];

        unsigned long long* mb = &g_mb[b * 1024];

        for (int k = 0; k <= NFSZ; k++) {
            const int par = k & 1, rp = par ^ 1;
            if (k + 1 <= NFSZ - 1) {
                const float* gp = &g_Gf[(k + 1) * G4 + u];
                #pragma unroll
                for (int g = 0; g < 4; g++) gfn[g] = gp[g * HSZ] + base_s[g];
            }
            float4 p0 = *(const float4*)&partA[rp][0];
            float4 p1 = *(const float4*)&partA[rp][4];
            float h_prev = ((p0.x + p0.y) + (p0.z + p0.w))
                         + ((p1.x + p1.y) + (p1.z + p1.w));
            if (k >= 1 && tid == 0)
                stv64(&mb[k - 1], packtv((unsigned)k, h_prev));
            if (k <= NFSZ - 1) {
                float pre0 = fmaf(whh_s[0], h_prev, gfc[0]);
                float pre1 = fmaf(whh_s[1], h_prev, gfc[1]);
                float pre2 = fmaf(whh_s[2], h_prev, gfc[2]);
                float pre3 = fmaf(whh_s[3], h_prev, gfc[3]);
                float ei = ex2f(pre0), ef = ex2f(pre1);
                float gs = pre2;
                float eg = ex2f(negabsf(gs));
                float eo = ex2f(pre3);
                float sf  = rcpf(1.f + ef);
                float mag = (1.f - eg) * rcpf((1.f + ei) * (1.f + eg));
                float itg = copysignf(mag, -gs);
                c = fmaf(sf, c, itg);
                float ec = ex2f(NL2E2 * fabsf(c));
                float hm = (1.f - ec) * rcpf((1.f + eo) * (1.f + ec));
                float hr = copysignf(hm, c);
                float partial = hr * whr;
                partial += __shfl_xor_sync(0xffffffffu, partial, 16);
                partial += __shfl_xor_sync(0xffffffffu, partial, 8);
                partial += __shfl_xor_sync(0xffffffffu, partial, 4);
                partial += __shfl_xor_sync(0xffffffffu, partial, 2);
                partial += __shfl_xor_sync(0xffffffffu, partial, 1);
                if (lane == 0) partA[par][warp] = partial;
            }
            #pragma unroll
            for (int g = 0; g < 4; g++) gfc[g] = gfn[g];
            __syncthreads();
        }
    } else {
        // ============ ROLE B : layer1 (bar 1) + layer2 (bar 2), decoupled ============
        const int wgi  = tid >> 7;           // 0 -> layer1, 1 -> layer2
        const int wtid = tid & 127;
        const int warp = wtid >> 5;
        const int lane = wtid & 31;
        const int u0   = wtid * 2;
        const int bar  = wgi + 1;

        const float* Whh = wgi ? Whh2 : Whh1;
        const float* Wih = wgi ? Wih2 : Wih1;
        const float* bih = wgi ? bih2 : bih1;
        const float* bhh = wgi ? bhh2 : bhh1;
        const float* Whr = wgi ? Whr2 : Whr1;
        const int skew = wgi ? 5 : 3;

        float whh_s[8], base_s[8], wih_s[8];
        #pragma unroll
        for (int j = 0; j < 8; j++) {
            int gate = j >> 1;
            int idx  = gate * HSZ + u0 + (j & 1);
            float sc = (gate == 2) ? NL2E2 : -L2E;
            whh_s[j]  = Whh[idx] * sc;
            base_s[j] = (bih[idx] + bhh[idx]) * sc;
            wih_s[j]  = Wih[idx] * sc;
        }
        const float w0 = Whr[u0], w1 = Whr[u0 + 1];
        float cs0 = 0.f, cs1 = 0.f;

        if (wtid < 16) { partB[0][wgi][wtid] = 0.f; partB[1][wgi][wtid] = 0.f; }
        for (int i = tid; i < NFSZ; i += 256) fwd[i] = 0ull;
        __syncthreads();   // one-time: init visible to both warpgroups

        const unsigned fwa = smaddr(&fwd[0]);
        unsigned long long* mbin = &g_mb[b * 1024];
        unsigned long long mv = (wgi == 0) ? ldv64(&mbin[0]) : 0ull;
        float* outp = out + b * NFSZ;

        for (int tk = 0; tk <= NFSZ + 5; tk++) {
            const int par = tk & 1, rp = par ^ 1;
            const int t = tk - skew;

            // materialize own h(t-1): 16 partials (guarded by this layer's bar)
            const float4* pp = (const float4*)partB[rp][wgi];
            float4 a = pp[0], q = pp[1], r = pp[2], d = pp[3];
            float h_prev = (((a.x + a.y) + (a.z + a.w)) + ((q.x + q.y) + (q.z + q.w)))
                         + (((r.x + r.y) + (r.z + r.w)) + ((d.x + d.y) + (d.z + d.w)));

            if (wtid == 0 && t >= 1 && t <= NFSZ) {
                if (wgi == 0)
                    stvs64(fwa + (t - 1) * 8, packtv((unsigned)t, h_prev));
                else
                    outp[t - 1] = h_prev;
            }

            if (t >= 0 && t < NFSZ) {
                float u_in;
                if (wgi == 0) {
                    const unsigned expf = (unsigned)(t + 1);
                    while ((unsigned)(mv >> 32) != expf) mv = ldv64(&mbin[t]);
                    u_in = valof(mv);
                    if (t + 1 < NFSZ) mv = ldv64(&mbin[t + 1]);   // prefetch
                } else {
                    const unsigned expf = (unsigned)(t + 1);
                    unsigned long long fv = ldvs64(fwa + t * 8);
                    while ((unsigned)(fv >> 32) != expf)
                        fv = ldvs64(fwa + t * 8);
                    u_in = valof(fv);
                }

                float pre[8];
                #pragma unroll
                for (int j = 0; j < 8; j++)
                    pre[j] = fmaf(whh_s[j], h_prev, fmaf(wih_s[j], u_in, base_s[j]));

                float partial = 0.f;
                #pragma unroll
                for (int m = 0; m < 2; m++) {
                    float ei = ex2f(pre[m]);
                    float ef = ex2f(pre[2 + m]);
                    float gs = pre[4 + m];
                    float eg = ex2f(negabsf(gs));
                    float eo = ex2f(pre[6 + m]);
                    float sf  = rcpf(1.f + ef);
                    float mag = (1.f - eg) * rcpf((1.f + ei) * (1.f + eg));
                    float itg = copysignf(mag, -gs);
                    float c = (m == 0) ? cs0 : cs1;
                    c = fmaf(sf, c, itg);
                    float ec = ex2f(NL2E2 * fabsf(c));
                    float hm = (1.f - ec) * rcpf((1.f + eo) * (1.f + ec));
                    float hr = copysignf(hm, c);
                    if (m == 0) { cs0 = c; partial = fmaf(hr, w0, partial); }
                    else        { cs1 = c; partial = fmaf(hr, w1, partial); }
                }
                partial += __shfl_xor_sync(0xffffffffu, partial, 16);
                partial += __shfl_xor_sync(0xffffffffu, partial, 8);
                partial += __shfl_xor_sync(0xffffffffu, partial, 4);
                if (lane < 4) partB[par][wgi][warp * 4 + lane] = partial;
            }
            // this layer's private 4-warp barrier (layers drift independently)
            asm volatile("bar.sync %0, 128;" :: "r"(bar) : "memory");
        }
    }
}

// ---------------- launch ----------------

extern "C" void kernel_launch(void* const* d_in, const int* in_sizes, int n_in,
                              void* d_out, int out_size) {
    const float* x    = (const float*)d_in[0];
    const float* f    = (const float*)d_in[1];
    const float* Wih0 = (const float*)d_in[2];
    const float* Whh0 = (const float*)d_in[3];
    const float* bih0 = (const float*)d_in[4];
    const float* bhh0 = (const float*)d_in[5];
    const float* Whr0 = (const float*)d_in[6];
    const float* Wih1 = (const float*)d_in[7];
    const float* Whh1 = (const float*)d_in[8];
    const float* bih1 = (const float*)d_in[9];
    const float* bhh1 = (const float*)d_in[10];
    const float* Whr1 = (const float*)d_in[11];
    const float* Wih2 = (const float*)d_in[12];
    const float* Whh2 = (const float*)d_in[13];
    const float* bih2 = (const float*)d_in[14];
    const float* bhh2 = (const float*)d_in[15];
    const float* Whr2 = (const float*)d_in[16];

    gf_kernel<<<dim3(126, 4), 256>>>(f, Wih0);
    lstm_kernel<<<2 * BSZ, 256>>>(x,
                                  Wih0, Whh0, bih0, bhh0, Whr0,
                                  Wih1, Whh1, bih1, bhh1, Whr1,
                                  Wih2, Whh2, bih2, bhh2, Whr2,
                                  (float*)d_out);
}

// round 11
// speedup vs baseline: 1.1582x; 1.1582x over previous
#include <cuda_runtime.h>

#define NFSZ 1001
#define HSZ   256
#define BSZ   64
#define FD    128
#define INCH  16
#define G4    1024   // 4*H
#define INS0  144    // FD + INCH

#define L2E   1.4426950408889634f
#define NL2E2 -2.8853900817779268f
#define KK    2.8853900817779268f   /* 2*log2(e) */

// device-global scratch (allocation-free rule)
// layout: g_Gf[t*G4 + u*4 + gate]  (unit-major, gates contiguous), pre-scaled
__device__ float g_Gf[NFSZ * G4];

__device__ __forceinline__ float ex2f(float x) {
    float y; asm("ex2.approx.f32 %0, %1;" : "=f"(y) : "f"(x)); return y;
}
__device__ __forceinline__ float rcpf(float x) {
    float y; asm("rcp.approx.f32 %0, %1;" : "=f"(y) : "f"(x)); return y;
}
__device__ __forceinline__ float negabsf(float x) {
    return __int_as_float(__float_as_int(x) | 0x80000000);
}
__device__ __forceinline__ unsigned smaddr(const void* p) {
    unsigned a;
    asm("{.reg .u64 t; cvta.to.shared.u64 t, %1; cvt.u32.u64 %0, t;}"
        : "=r"(a) : "l"(p));
    return a;
}
__device__ __forceinline__ unsigned long long ldvs64(unsigned a) {
    unsigned long long v;
    asm volatile("ld.volatile.shared.b64 %0, [%1];" : "=l"(v) : "r"(a));
    return v;
}
__device__ __forceinline__ void stvs64(unsigned a, unsigned long long v) {
    asm volatile("st.volatile.shared.b64 [%0], %1;" :: "r"(a), "l"(v));
}
__device__ __forceinline__ unsigned long long packtv(unsigned tag, float val) {
    return ((unsigned long long)tag << 32) | (unsigned)__float_as_int(val);
}
__device__ __forceinline__ float valof(unsigned long long v) {
    return __int_as_float((int)(unsigned)v);
}

// ---------------- precompute: Gf[t][u][gate] = scale(gate) * (f[t] . Wf[gate*256+u]) ----------------
__global__ __launch_bounds__(256) void gf_kernel(const float* __restrict__ f,
                                                 const float* __restrict__ Wih0) {
    __shared__ float Wc[256][33];
    __shared__ float fs[8][32];
    const int tid = threadIdx.x;            // unit 0..255
    const int t0  = blockIdx.x * 8;
    const int gy  = blockIdx.y;             // gate 0..3
    const int gb  = gy * 256;

    float acc[8] = {0.f,0.f,0.f,0.f,0.f,0.f,0.f,0.f};
    for (int kc = 0; kc < FD; kc += 32) {
        #pragma unroll
        for (int i = 0; i < 32; i++) {
            int e  = i * 256 + tid;
            int gl = e >> 5, kk = e & 31;
            Wc[gl][kk] = Wih0[(gb + gl) * INS0 + kc + kk];
        }
        {
            int tt = tid >> 5, kk = tid & 31;
            int t = t0 + tt;
            fs[tt][kk] = (t < NFSZ) ? f[t * FD + kc + kk] : 0.f;
        }
        __syncthreads();
        #pragma unroll 8
        for (int kk = 0; kk < 32; kk++) {
            float w = Wc[tid][kk];
            #pragma unroll
            for (int tt = 0; tt < 8; tt++) acc[tt] = fmaf(fs[tt][kk], w, acc[tt]);
        }
        __syncthreads();
    }
    float scale = (gy == 2) ? NL2E2 : -L2E;
    #pragma unroll
    for (int tt = 0; tt < 8; tt++) {
        int t = t0 + tt;
        if (t < NFSZ) g_Gf[t * G4 + tid * 4 + gy] = acc[tt] * scale;
    }
}

// ---------------- main LSTM: one WARP per layer, zero sync in recurrence ----------------
// 64 CTAs (one per batch) x 96 threads. Warp w = layer w (distinct SMSPs).
// 8 hidden units per thread. The 5-level shfl butterfly leaves h in every
// lane's registers -> next tick needs NO memory and NO barrier.
// Inter-layer scalars: full-length tagged smem rings (slot t tagged t+1).
// Activation math = R4's paired-rcp form (correctness-proven, 48 MUFU/tick).

__global__ __launch_bounds__(96, 1) void lstm_kernel(
    const float* __restrict__ x,
    const float* __restrict__ Wih0, const float* __restrict__ Whh0,
    const float* __restrict__ bih0, const float* __restrict__ bhh0,
    const float* __restrict__ Whr0,
    const float* __restrict__ Wih1, const float* __restrict__ Whh1,
    const float* __restrict__ bih1, const float* __restrict__ bhh1,
    const float* __restrict__ Whr1,
    const float* __restrict__ Wih2, const float* __restrict__ Whh2,
    const float* __restrict__ bih2, const float* __restrict__ bhh2,
    const float* __restrict__ Whr2,
    float* __restrict__ out)
{
    __shared__ unsigned long long ring[2][NFSZ];   // [boundary 0->1, 1->2]

    const int b    = blockIdx.x;
    const int tid  = threadIdx.x;
    const int wid  = tid >> 5;          // layer id 0..2
    const int lane = tid & 31;
    const int u0   = lane * 8;          // 8 consecutive units per thread

    // init rings (tags = 0, never matches t+1 >= 1)
    for (int i = tid; i < 2 * NFSZ; i += 96)
        ((unsigned long long*)ring)[i] = 0ull;
    __syncthreads();   // one-time; the recurrence below is sync-free

    const float* Whh  = (wid == 0) ? Whh0 : (wid == 1) ? Whh1 : Whh2;
    const float* Wih  = (wid == 2) ? Wih2 : Wih1;
    const float* bihp = (wid == 0) ? bih0 : (wid == 1) ? bih1 : bih2;
    const float* bhhp = (wid == 0) ? bhh0 : (wid == 1) ? bhh1 : bhh2;
    const float* Whrp = (wid == 0) ? Whr0 : (wid == 1) ? Whr1 : Whr2;

    // j = r*4 + gate  (unit r = 0..7 within thread, gate 0=i,1=f,2=g,3=o)
    float whh[32], base[32], wih[32];
    #pragma unroll
    for (int r = 0; r < 8; r++) {
        #pragma unroll
        for (int g = 0; g < 4; g++) {
            const int j   = r * 4 + g;
            const int idx = g * HSZ + u0 + r;
            const float sc = (g == 2) ? NL2E2 : -L2E;
            whh[j] = Whh[idx] * sc;
            float acc = bihp[idx] + bhhp[idx];
            if (wid == 0) {
                #pragma unroll
                for (int kk = 0; kk < INCH; kk++)
                    acc = fmaf(x[b * INCH + kk], Wih0[idx * INS0 + FD + kk], acc);
                wih[j] = 0.f;
            } else {
                wih[j] = Wih[idx] * sc;
            }
            base[j] = acc * sc;
        }
    }
    float awhr[8], cs[8];
    int   sgn[8];
    #pragma unroll
    for (int r = 0; r < 8; r++) {
        float w = Whrp[u0 + r];
        awhr[r] = fabsf(w);
        sgn[r]  = __float_as_int(w) & 0x80000000;
        cs[r]   = 0.f;                 // scaled cell state: 2*log2e * c
    }

    const unsigned rin  = smaddr(&ring[wid - 1][0]);   // used when wid>0
    const unsigned rout = smaddr(&ring[wid][0]);       // used when wid<2
    float* outp = out + b * NFSZ;
    float h_prev = 0.f;

    // paired-unit activation body (R4 formulas). pre in pA/pB, updates cs, adds to partial.
#define PAIR_BODY(RA, RB, PA, PB, PARTIAL)                                     \
    {                                                                          \
        float eiA = ex2f(PA[0]), efA = ex2f(PA[1]);                            \
        float gsA = PA[2];                                                     \
        float egA = ex2f(negabsf(gsA));                                        \
        float eoA = ex2f(PA[3]);                                               \
        float p1A = 1.f + eiA, p2A = 1.f + egA, p3A = 1.f + efA;               \
        float PPA = p1A * p2A, DA = PPA * p3A;                                 \
        float t2A = fmaf(egA, -KK, KK) * p3A;                                  \
        float numA = fmaf(cs[RA], PPA, copysignf(t2A, -gsA));                  \
        float eiB = ex2f(PB[0]), efB = ex2f(PB[1]);                            \
        float gsB = PB[2];                                                     \
        float egB = ex2f(negabsf(gsB));                                        \
        float eoB = ex2f(PB[3]);                                               \
        float p1B = 1.f + eiB, p2B = 1.f + egB, p3B = 1.f + efB;               \
        float PPB = p1B * p2B, DB = PPB * p3B;                                 \
        float t2B = fmaf(egB, -KK, KK) * p3B;                                  \
        float numB = fmaf(cs[RB], PPB, copysignf(t2B, -gsB));                  \
        float R = rcpf(DA * DB);                                               \
        float csA = numA * (R * DB);                                           \
        float csB = numB * (R * DA);                                           \
        cs[RA] = csA; cs[RB] = csB;                                            \
        float ecA = ex2f(negabsf(csA)), ecB = ex2f(negabsf(csB));              \
        float EA = (1.f + ecA) * (1.f + eoA);                                  \
        float EB = (1.f + ecB) * (1.f + eoB);                                  \
        float A7A = fmaf(ecA, -awhr[RA], awhr[RA]);                            \
        float A7B = fmaf(ecB, -awhr[RB], awhr[RB]);                            \
        float R2 = rcpf(EA * EB);                                              \
        float cAt = A7A * (R2 * EB);                                           \
        float cBt = A7B * (R2 * EA);                                           \
        float sA = __int_as_float(__float_as_int(csA) ^ sgn[RA]);              \
        float sB = __int_as_float(__float_as_int(csB) ^ sgn[RB]);              \
        PARTIAL += copysignf(cAt, sA) + copysignf(cBt, sB);                    \
    }

    if (wid == 0) {
        // ---- layer 0: Gf-table input, register double-buffer prefetch ----
        float gfc[32];
        {
            const float* g0 = &g_Gf[u0 * 4];
            #pragma unroll
            for (int q = 0; q < 8; q++) {
                float4 v = *(const float4*)(g0 + q * 4);
                gfc[q * 4 + 0] = v.x + base[q * 4 + 0];
                gfc[q * 4 + 1] = v.y + base[q * 4 + 1];
                gfc[q * 4 + 2] = v.z + base[q * 4 + 2];
                gfc[q * 4 + 3] = v.w + base[q * 4 + 3];
            }
        }
        const float* gp = &g_Gf[G4 + u0 * 4];

        for (int t = 0; t < NFSZ; t++) {
            float gfn[32];
            const bool more = (t + 1 < NFSZ);
            if (more) {
                #pragma unroll
                for (int q = 0; q < 8; q++) {
                    float4 v = *(const float4*)(gp + q * 4);
                    gfn[q * 4 + 0] = v.x + base[q * 4 + 0];
                    gfn[q * 4 + 1] = v.y + base[q * 4 + 1];
                    gfn[q * 4 + 2] = v.z + base[q * 4 + 2];
                    gfn[q * 4 + 3] = v.w + base[q * 4 + 3];
                }
                gp += G4;
            }
            float partial = 0.f;
            #pragma unroll
            for (int p = 0; p < 4; p++) {
                const int rA = 2 * p, rB = 2 * p + 1;
                float pA[4], pB[4];
                #pragma unroll
                for (int g = 0; g < 4; g++) {
                    pA[g] = fmaf(whh[rA * 4 + g], h_prev, gfc[rA * 4 + g]);
                    pB[g] = fmaf(whh[rB * 4 + g], h_prev, gfc[rB * 4 + g]);
                }
                PAIR_BODY(rA, rB, pA, pB, partial)
            }
            partial += __shfl_xor_sync(0xffffffffu, partial, 16);
            partial += __shfl_xor_sync(0xffffffffu, partial, 8);
            partial += __shfl_xor_sync(0xffffffffu, partial, 4);
            partial += __shfl_xor_sync(0xffffffffu, partial, 2);
            partial += __shfl_xor_sync(0xffffffffu, partial, 1);
            h_prev = partial;                      // every lane holds h(t)
            if (lane == 0)
                stvs64(rout + t * 8, packtv((unsigned)(t + 1), h_prev));
            if (more) {
                #pragma unroll
                for (int j = 0; j < 32; j++) gfc[j] = gfn[j];
            }
        }
    } else {
        // ---- layers 1 & 2: scalar input from ring ----
        for (int t = 0; t < NFSZ; t++) {
            const unsigned a = rin + t * 8;
            const unsigned expf = (unsigned)(t + 1);
            unsigned long long v = ldvs64(a);
            while ((unsigned)(v >> 32) != expf) v = ldvs64(a);
            const float u_in = valof(v);

            float partial = 0.f;
            #pragma unroll
            for (int p = 0; p < 4; p++) {
                const int rA = 2 * p, rB = 2 * p + 1;
                float pA[4], pB[4];
                #pragma unroll
                for (int g = 0; g < 4; g++) {
                    pA[g] = fmaf(whh[rA * 4 + g], h_prev,
                                 fmaf(wih[rA * 4 + g], u_in, base[rA * 4 + g]));
                    pB[g] = fmaf(whh[rB * 4 + g], h_prev,
                                 fmaf(wih[rB * 4 + g], u_in, base[rB * 4 + g]));
                }
                PAIR_BODY(rA, rB, pA, pB, partial)
            }
            partial += __shfl_xor_sync(0xffffffffu, partial, 16);
            partial += __shfl_xor_sync(0xffffffffu, partial, 8);
            partial += __shfl_xor_sync(0xffffffffu, partial, 4);
            partial += __shfl_xor_sync(0xffffffffu, partial, 2);
            partial += __shfl_xor_sync(0xffffffffu, partial, 1);
            h_prev = partial;
            if (wid == 1) {
                if (lane == 0)
                    stvs64(rout + t * 8, packtv((unsigned)(t + 1), h_prev));
            } else {
                if (lane == 0) outp[t] = h_prev;
            }
        }
    }
#undef PAIR_BODY
}

// ---------------- launch ----------------

extern "C" void kernel_launch(void* const* d_in, const int* in_sizes, int n_in,
                              void* d_out, int out_size) {
    const float* x    = (const float*)d_in[0];
    const float* f    = (const float*)d_in[1];
    const float* Wih0 = (const float*)d_in[2];
    const float* Whh0 = (const float*)d_in[3];
    const float* bih0 = (const float*)d_in[4];
    const float* bhh0 = (const float*)d_in[5];
    const float* Whr0 = (const float*)d_in[6];
    const float* Wih1 = (const float*)d_in[7];
    const float* Whh1 = (const float*)d_in[8];
    const float* bih1 = (const float*)d_in[9];
    const float* bhh1 = (const float*)d_in[10];
    const float* Whr1 = (const float*)d_in[11];
    const float* Wih2 = (const float*)d_in[12];
    const float* Whh2 = (const float*)d_in[13];
    const float* bih2 = (const float*)d_in[14];
    const float* bhh2 = (const float*)d_in[15];
    const float* Whr2 = (const float*)d_in[16];

    gf_kernel<<<dim3(126, 4), 256>>>(f, Wih0);
    lstm_kernel<<<BSZ, 96>>>(x,
                             Wih0, Whh0, bih0, bhh0, Whr0,
                             Wih1, Whh1, bih1, bhh1, Whr1,
                             Wih2, Whh2, bih2, bhh2, Whr2,
                             (float*)d_out);
}

// round 13
// speedup vs baseline: 1.9434x; 1.6779x over previous
#include <cuda_runtime.h>

#define NFSZ 1001
#define HSZ   256
#define BSZ   64
#define FD    128
#define INCH  16
#define G4    1024   // 4*H
#define INS0  144    // FD + INCH

// device-global scratch (allocation-free rule)
__device__ float g_Gf[NFSZ * G4];                // pre-scaled f-side gate pre-acts
__device__ unsigned long long g_mb[BSZ * 1024];  // layer0->layer1 mailbox {tag,val}

__device__ __forceinline__ float ex2f(float x) {
    float y; asm("ex2.approx.f32 %0, %1;" : "=f"(y) : "f"(x)); return y;
}
__device__ __forceinline__ float rcpf(float x) {
    float y; asm("rcp.approx.f32 %0, %1;" : "=f"(y) : "f"(x)); return y;
}
__device__ __forceinline__ float negabsf(float x) {
    return __int_as_float(__float_as_int(x) | 0x80000000);
}
__device__ __forceinline__ unsigned long long ldv64(const unsigned long long* p) {
    unsigned long long v;
    asm volatile("ld.volatile.global.b64 %0, [%1];" : "=l"(v) : "l"(p));
    return v;
}
__device__ __forceinline__ void stv64(unsigned long long* p, unsigned long long v) {
    asm volatile("st.volatile.global.b64 [%0], %1;" :: "l"(p), "l"(v) : "memory");
}
__device__ __forceinline__ unsigned long long packtv(unsigned tag, float val) {
    return ((unsigned long long)tag << 32) | (unsigned)__float_as_int(val);
}
__device__ __forceinline__ float valof(unsigned long long v) {
    return __int_as_float((int)(unsigned)v);
}

#define L2E   1.4426950408889634f
#define NL2E2 -2.8853900817779268f

// ---------------- precompute: Gf = scale * (f @ Wf^T)  (layout [t][gate*256+u]) ----------------
__global__ __launch_bounds__(256) void gf_kernel(const float* __restrict__ f,
                                                 const float* __restrict__ Wih0) {
    __shared__ float Wc[256][33];
    __shared__ float fs[8][32];
    const int tid = threadIdx.x;
    const int t0  = blockIdx.x * 8;
    const int gb  = blockIdx.y * 256;

    float acc[8] = {0.f,0.f,0.f,0.f,0.f,0.f,0.f,0.f};
    for (int kc = 0; kc < FD; kc += 32) {
        #pragma unroll
        for (int i = 0; i < 32; i++) {
            int e  = i * 256 + tid;
            int gl = e >> 5, kk = e & 31;
            Wc[gl][kk] = Wih0[(gb + gl) * INS0 + kc + kk];
        }
        {
            int tt = tid >> 5, kk = tid & 31;
            int t = t0 + tt;
            fs[tt][kk] = (t < NFSZ) ? f[t * FD + kc + kk] : 0.f;
        }
        __syncthreads();
        #pragma unroll 8
        for (int kk = 0; kk < 32; kk++) {
            float w = Wc[tid][kk];
            #pragma unroll
            for (int tt = 0; tt < 8; tt++) acc[tt] = fmaf(fs[tt][kk], w, acc[tt]);
        }
        __syncthreads();
    }
    float scale = (blockIdx.y == 2) ? NL2E2 : -L2E;
    #pragma unroll
    for (int tt = 0; tt < 8; tt++) {
        int t = t0 + tt;
        if (t < NFSZ) g_Gf[t * G4 + gb + tid] = acc[tt] * scale;
    }
}

// ---------------- main LSTM: 2 CTAs per batch (R5-proven structure) ----------------
// blk even -> role A (layer0: 256 thr, 1 unit/thread, __syncthreads lockstep)
// blk odd  -> role B (layers 1+2 as two 128-thr warpgroups, shared __syncthreads)
// A->B link: tagged gmem mailbox, 3-tick skew, prefetched.
// B-internal layer1->layer2: smem parity scalar, 2-tick relative skew.
// Activation: 7-MUFU independent-chain form (single rcp for the c-update).

__global__ __launch_bounds__(256, 1) void lstm_kernel(
    const float* __restrict__ x,
    const float* __restrict__ Wih0, const float* __restrict__ Whh0,
    const float* __restrict__ bih0, const float* __restrict__ bhh0,
    const float* __restrict__ Whr0,
    const float* __restrict__ Wih1, const float* __restrict__ Whh1,
    const float* __restrict__ bih1, const float* __restrict__ bhh1,
    const float* __restrict__ Whr1,
    const float* __restrict__ Wih2, const float* __restrict__ Whh2,
    const float* __restrict__ bih2, const float* __restrict__ bhh2,
    const float* __restrict__ Whr2,
    float* __restrict__ out)
{
    __shared__ __align__(16) float partA[2][8];      // role A: one partial per warp
    __shared__ __align__(16) float partB[2][2][16];  // role B: [parity][layer][16]
    __shared__ float fwdB[2];                        // layer1 -> layer2 scalar

    const int b    = blockIdx.x >> 1;
    const int role = blockIdx.x & 1;
    const int tid  = threadIdx.x;

    if (role == 0) {
        // ================= ROLE A : layer 0, 1 unit per thread =================
        const int u    = tid;
        const int warp = tid >> 5;
        const int lane = tid & 31;

        float whh_s[4], base_s[4];
        #pragma unroll
        for (int g = 0; g < 4; g++) {
            int idx  = g * HSZ + u;
            float sc = (g == 2) ? NL2E2 : -L2E;
            whh_s[g] = Whh0[idx] * sc;
            float acc = bih0[idx] + bhh0[idx];
            #pragma unroll
            for (int kk = 0; kk < INCH; kk++)
                acc = fmaf(x[b * INCH + kk], Wih0[idx * INS0 + FD + kk], acc);
            base_s[g] = acc * sc;
        }
        const float whr = Whr0[u];
        float c = 0.f;

        if (tid < 8)  { partA[0][tid] = 0.f; partA[1][tid] = 0.f; }
        __syncthreads();

        float gfc[4], gfn[4];
        #pragma unroll
        for (int g = 0; g < 4; g++) gfc[g] = g_Gf[g * HSZ + u] + base_s[g];

        unsigned long long* mb = &g_mb[b * 1024];

        for (int k = 0; k <= NFSZ; k++) {
            const int par = k & 1, rp = par ^ 1;
            // off-chain prefetch of next Gf row (pre-added with base)
            if (k + 1 <= NFSZ - 1) {
                const float* gp = &g_Gf[(k + 1) * G4 + u];
                #pragma unroll
                for (int g = 0; g < 4; g++) gfn[g] = gp[g * HSZ] + base_s[g];
            }
            // h_prev = output(k-1): sum 8 warp partials
            float4 p0 = *(const float4*)&partA[rp][0];
            float4 p1 = *(const float4*)&partA[rp][4];
            float h_prev = ((p0.x + p0.y) + (p0.z + p0.w))
                         + ((p1.x + p1.y) + (p1.z + p1.w));
            if (k >= 1 && tid == 0)
                stv64(&mb[k - 1], packtv((unsigned)k, h_prev));
            if (k <= NFSZ - 1) {
                float pre0 = fmaf(whh_s[0], h_prev, gfc[0]);
                float pre1 = fmaf(whh_s[1], h_prev, gfc[1]);
                float pre2 = fmaf(whh_s[2], h_prev, gfc[2]);
                float pre3 = fmaf(whh_s[3], h_prev, gfc[3]);
                // 7-MUFU activation: single rcp for the whole c-update
                float ei = ex2f(pre0), ef = ex2f(pre1), eo = ex2f(pre3);
                float eg = ex2f(negabsf(pre2));
                float pi = 1.f + ei, pf = 1.f + ef, pg = 1.f + eg;
                float PP = pi * pg;
                float R  = rcpf(PP * pf);
                float tnum = fmaf(eg, -pf, pf);                 // (1-eg)*pf
                float num  = fmaf(c, PP, copysignf(tnum, -pre2));
                c = num * R;
                float ec = ex2f(NL2E2 * fabsf(c));
                float hm = fmaf(ec, -1.f, 1.f) * rcpf((1.f + eo) * (1.f + ec));
                float hr = copysignf(hm, c);
                float partial = hr * whr;
                partial += __shfl_xor_sync(0xffffffffu, partial, 16);
                partial += __shfl_xor_sync(0xffffffffu, partial, 8);
                partial += __shfl_xor_sync(0xffffffffu, partial, 4);
                partial += __shfl_xor_sync(0xffffffffu, partial, 2);
                partial += __shfl_xor_sync(0xffffffffu, partial, 1);
                if (lane == 0) partA[par][warp] = partial;
            }
            #pragma unroll
            for (int g = 0; g < 4; g++) gfc[g] = gfn[g];
            __syncthreads();
        }
    } else {
        // ============ ROLE B : layers 1 (wg0, t=k-3) + 2 (wg1, t=k-5) ============
        const int wg   = tid >> 7;          // 0 -> layer1, 1 -> layer2
        const int wtid = tid & 127;
        const int warp = wtid >> 5;
        const int lane = wtid & 31;
        const int u0   = wtid * 2;

        const float* Whh = wg ? Whh2 : Whh1;
        const float* Wih = wg ? Wih2 : Wih1;
        const float* bih = wg ? bih2 : bih1;
        const float* bhh = wg ? bhh2 : bhh1;
        const float* Whr = wg ? Whr2 : Whr1;
        const int skew = wg ? 5 : 3;

        float whh_s[8], base_s[8], wih_s[8];
        #pragma unroll
        for (int j = 0; j < 8; j++) {
            int gate = j >> 1;
            int idx  = gate * HSZ + u0 + (j & 1);
            float sc = (gate == 2) ? NL2E2 : -L2E;
            whh_s[j]  = Whh[idx] * sc;
            base_s[j] = (bih[idx] + bhh[idx]) * sc;
            wih_s[j]  = Wih[idx] * sc;
        }
        const float w0 = Whr[u0], w1 = Whr[u0 + 1];
        float cs0 = 0.f, cs1 = 0.f;

        if (wtid < 16) { partB[0][wg][wtid] = 0.f; partB[1][wg][wtid] = 0.f; }
        if (tid < 2)   fwdB[tid] = 0.f;
        __syncthreads();

        unsigned long long* mbin = &g_mb[b * 1024];
        unsigned long long mv = 0;   // prefetched mailbox word (layer1 only)

        for (int k = 0; k <= NFSZ + 5; k++) {
            const int par = k & 1, rp = par ^ 1;
            const int t = k - skew;
            const bool active = (t >= 0) && (t < NFSZ);

            // own h_prev: sum 16 partials
            float h_prev;
            {
                const float4* p = (const float4*)partB[rp][wg];
                float4 a = p[0], q = p[1], r = p[2], d = p[3];
                h_prev = (((a.x + a.y) + (a.z + a.w)) + ((q.x + q.y) + (q.z + q.w)))
                       + (((r.x + r.y) + (r.z + r.w)) + ((d.x + d.y) + (d.z + d.w)));
            }
            // inter-layer input scalar
            float u_in = 0.f;
            if (wg == 0) {
                if (active) {
                    unsigned exp_flag = (unsigned)(t + 1);
                    while ((unsigned)(mv >> 32) != exp_flag) mv = ldv64(&mbin[t]);
                    u_in = valof(mv);
                }
                if (wtid == 0) fwdB[par] = h_prev;   // forward to layer2
            } else {
                u_in = fwdB[rp];
                if (wtid == 0 && k >= 6) out[b * NFSZ + (k - 6)] = h_prev;
            }

            if (active) {
                float pre[8];
                #pragma unroll
                for (int j = 0; j < 8; j++)
                    pre[j] = fmaf(whh_s[j], h_prev, fmaf(wih_s[j], u_in, base_s[j]));
                float partial = 0.f;
                #pragma unroll
                for (int m = 0; m < 2; m++) {
                    float ei = ex2f(pre[m]);
                    float ef = ex2f(pre[2 + m]);
                    float gs = pre[4 + m];
                    float eg = ex2f(negabsf(gs));
                    float eo = ex2f(pre[6 + m]);
                    float pi = 1.f + ei, pf = 1.f + ef, pg = 1.f + eg;
                    float PP = pi * pg;
                    float R  = rcpf(PP * pf);
                    float tnum = fmaf(eg, -pf, pf);
                    float c = (m == 0) ? cs0 : cs1;
                    float num = fmaf(c, PP, copysignf(tnum, -gs));
                    c = num * R;
                    float ec = ex2f(NL2E2 * fabsf(c));
                    float hm = fmaf(ec, -1.f, 1.f) * rcpf((1.f + eo) * (1.f + ec));
                    float hr = copysignf(hm, c);
                    if (m == 0) { cs0 = c; partial = fmaf(hr, w0, partial); }
                    else        { cs1 = c; partial = fmaf(hr, w1, partial); }
                }
                partial += __shfl_xor_sync(0xffffffffu, partial, 16);
                partial += __shfl_xor_sync(0xffffffffu, partial, 8);
                partial += __shfl_xor_sync(0xffffffffu, partial, 4);
                if (lane < 4) partB[par][wg][warp * 4 + lane] = partial;
            }
            // layer1: prefetch next tick's mailbox word (off-chain; spin at use)
            if (wg == 0) {
                int tn = t + 1;
                if (tn >= 0 && tn < NFSZ) mv = ldv64(&mbin[tn]);
            }
            __syncthreads();
        }
    }
}

// ---------------- launch ----------------

extern "C" void kernel_launch(void* const* d_in, const int* in_sizes, int n_in,
                              void* d_out, int out_size) {
    const float* x    = (const float*)d_in[0];
    const float* f    = (const float*)d_in[1];
    const float* Wih0 = (const float*)d_in[2];
    const float* Whh0 = (const float*)d_in[3];
    const float* bih0 = (const float*)d_in[4];
    const float* bhh0 = (const float*)d_in[5];
    const float* Whr0 = (const float*)d_in[6];
    const float* Wih1 = (const float*)d_in[7];
    const float* Whh1 = (const float*)d_in[8];
    const float* bih1 = (const float*)d_in[9];
    const float* bhh1 = (const float*)d_in[10];
    const float* Whr1 = (const float*)d_in[11];
    const float* Wih2 = (const float*)d_in[12];
    const float* Whh2 = (const float*)d_in[13];
    const float* bih2 = (const float*)d_in[14];
    const float* bhh2 = (const float*)d_in[15];
    const float* Whr2 = (const float*)d_in[16];

    gf_kernel<<<dim3(126, 4), 256>>>(f, Wih0);
    lstm_kernel<<<2 * BSZ, 256>>>(x,
                                  Wih0, Whh0, bih0, bhh0, Whr0,
                                  Wih1, Whh1, bih1, bhh1, Whr1,
                                  Wih2, Whh2, bih2, bhh2, Whr2,
                                  (float*)d_out);
}